// round 1
// baseline (speedup 1.0000x reference)
#include <cuda_runtime.h>

#define N_NODES 50000
#define N_EDGES 600000
#define IN_CH 128
#define HC 128
#define HEADS 4
#define CPH 32
#define NEG_SLOPE 0.2f
#define NPB 32   // nodes per block in transform kernel

// ---------------- scratch (device globals; no allocations allowed) ----------
__device__ float    g_Wt[IN_CH * HC];          // W transposed: [i][o]
__device__ float    g_bias[HC];
__device__ float    g_asrc[HC];                // [h][c]
__device__ float    g_adst[HC];
__device__ float    g_xt[(size_t)N_NODES * HC];        // 25.6 MB, L2-resident
__device__ float    g_alpha_src[N_NODES * HEADS];
__device__ float    g_alpha_dst[N_NODES * HEADS];
__device__ float    g_alpha[(size_t)N_EDGES * HEADS];  // 9.6 MB (alpha, then ex)
__device__ unsigned g_amax[N_NODES * HEADS];           // ordered-uint encoded max
__device__ float    g_denom[N_NODES * HEADS];

// ordered-uint encoding so unsigned atomicMax == float max (handles negatives)
__device__ __forceinline__ unsigned f2ord(float f) {
    unsigned u = __float_as_uint(f);
    return (u & 0x80000000u) ? ~u : (u | 0x80000000u);
}
__device__ __forceinline__ float ord2f(unsigned k) {
    unsigned u = (k & 0x80000000u) ? (k & 0x7fffffffu) : ~k;
    return __uint_as_float(u);
}

// ---------------- kernel 1: Bezier parameter interpolation ------------------
__global__ void k_prep(const float* __restrict__ lw, const float* __restrict__ lb,
                       const float* __restrict__ as, const float* __restrict__ ad,
                       const float* __restrict__ ct) {
    float c0 = ct[0], c1 = ct[1], c2 = ct[2];
    for (int idx = blockIdx.x * blockDim.x + threadIdx.x; idx < IN_CH * HC;
         idx += gridDim.x * blockDim.x) {
        int i = idx / HC;        // input channel
        int o = idx % HC;        // output channel
        // lin_weight layout: [B][o][i]
        g_Wt[idx] = c0 * lw[o * IN_CH + i]
                  + c1 * lw[IN_CH * HC + o * IN_CH + i]
                  + c2 * lw[2 * IN_CH * HC + o * IN_CH + i];
        if (idx < HC) {
            g_bias[idx] = c0 * lb[idx] + c1 * lb[HC + idx] + c2 * lb[2 * HC + idx];
            g_asrc[idx] = c0 * as[idx] + c1 * as[HC + idx] + c2 * as[2 * HC + idx];
            g_adst[idx] = c0 * ad[idx] + c1 * ad[HC + idx] + c2 * ad[2 * HC + idx];
        }
    }
}

// ---------------- kernel 2: zero/init -----------------------------------
__global__ void k_init(float* __restrict__ out) {
    int i = blockIdx.x * blockDim.x + threadIdx.x;
    if (i < N_NODES * HC) out[i] = 0.0f;
    if (i < N_NODES * HEADS) { g_denom[i] = 0.0f; g_amax[i] = 0u; }
}

// ---------------- kernel 3: node transform + attention coefficients ---------
// Block = 32 nodes, 128 threads; thread t owns output column t across all 32
// nodes (register accumulators). x tile in smem (broadcast reads, no conflicts),
// Wt rows are coalesced 128B warp loads (L1-hot: Wt is 64KB).
__global__ void __launch_bounds__(128) k_xt(const float* __restrict__ x) {
    __shared__ float xs[NPB][IN_CH];
    int n0 = blockIdx.x * NPB;
    int t = threadIdx.x;

    #pragma unroll
    for (int n = 0; n < NPB; n++) {
        int node = n0 + n;
        xs[n][t] = (node < N_NODES) ? x[(size_t)node * IN_CH + t] : 0.0f;
    }
    __syncthreads();

    float acc[NPB];
    float b = g_bias[t];
    #pragma unroll
    for (int n = 0; n < NPB; n++) acc[n] = b;

    #pragma unroll 4
    for (int i = 0; i < IN_CH; i++) {
        float w = g_Wt[i * HC + t];
        #pragma unroll
        for (int n = 0; n < NPB; n++) acc[n] += xs[n][i] * w;
    }

    // write xt (coalesced)
    #pragma unroll
    for (int n = 0; n < NPB; n++) {
        int node = n0 + n;
        if (node < N_NODES) g_xt[(size_t)node * HC + t] = acc[n];
    }

    // per-head attention dot products: warp w == head w, lane == channel
    int h = t >> 5;
    int c = t & 31;
    float a_s = g_asrc[t];
    float a_d = g_adst[t];
    #pragma unroll
    for (int n = 0; n < NPB; n++) {
        float vs = acc[n] * a_s;
        float vd = acc[n] * a_d;
        #pragma unroll
        for (int off = 16; off > 0; off >>= 1) {
            vs += __shfl_xor_sync(0xffffffffu, vs, off);
            vd += __shfl_xor_sync(0xffffffffu, vd, off);
        }
        if (c == 0) {
            int node = n0 + n;
            if (node < N_NODES) {
                g_alpha_src[node * HEADS + h] = vs;
                g_alpha_dst[node * HEADS + h] = vd;
            }
        }
    }
}

// ---------------- kernel 4: edge alpha + segment max -------------------------
__global__ void k_edge_alpha(const int* __restrict__ ei) {
    int e = blockIdx.x * blockDim.x + threadIdx.x;
    if (e >= N_EDGES) return;
    int r = ei[e];
    int c = ei[N_EDGES + e];
    float4 as = ((const float4*)g_alpha_src)[r];
    float4 ad = ((const float4*)g_alpha_dst)[c];
    float4 a;
    a.x = as.x + ad.x; a.x = (a.x > 0.f) ? a.x : NEG_SLOPE * a.x;
    a.y = as.y + ad.y; a.y = (a.y > 0.f) ? a.y : NEG_SLOPE * a.y;
    a.z = as.z + ad.z; a.z = (a.z > 0.f) ? a.z : NEG_SLOPE * a.z;
    a.w = as.w + ad.w; a.w = (a.w > 0.f) ? a.w : NEG_SLOPE * a.w;
    ((float4*)g_alpha)[e] = a;
    atomicMax(&g_amax[c * 4 + 0], f2ord(a.x));
    atomicMax(&g_amax[c * 4 + 1], f2ord(a.y));
    atomicMax(&g_amax[c * 4 + 2], f2ord(a.z));
    atomicMax(&g_amax[c * 4 + 3], f2ord(a.w));
}

// ---------------- kernel 5: exp + segment sum (denominator) ------------------
__global__ void k_edge_exp(const int* __restrict__ ei) {
    int e = blockIdx.x * blockDim.x + threadIdx.x;
    if (e >= N_EDGES) return;
    int c = ei[N_EDGES + e];
    float4 a = ((const float4*)g_alpha)[e];
    uint4 k = ((const uint4*)g_amax)[c];
    float4 ex;
    ex.x = __expf(a.x - ord2f(k.x));
    ex.y = __expf(a.y - ord2f(k.y));
    ex.z = __expf(a.z - ord2f(k.z));
    ex.w = __expf(a.w - ord2f(k.w));
    ((float4*)g_alpha)[e] = ex;   // overwrite with numerator
    atomicAdd(&g_denom[c * 4 + 0], ex.x);
    atomicAdd(&g_denom[c * 4 + 1], ex.y);
    atomicAdd(&g_denom[c * 4 + 2], ex.z);
    atomicAdd(&g_denom[c * 4 + 3], ex.w);
}

// ---------------- kernel 6: weighted aggregation ------------------------------
// One warp per edge; lane l covers output floats [4l, 4l+4) (head = l/8).
__global__ void k_agg(const int* __restrict__ ei, float* __restrict__ out) {
    long long gt = (long long)blockIdx.x * blockDim.x + threadIdx.x;
    int e = (int)(gt >> 5);
    if (e >= N_EDGES) return;
    int lane = (int)(gt & 31);
    int r = ei[e];
    int c = ei[N_EDGES + e];
    int h = lane >> 3;
    float ex = g_alpha[(size_t)e * 4 + h];
    float dn = g_denom[c * 4 + h];
    float w = ex / (dn + 1e-16f);
    float4 v = ((const float4*)g_xt)[(size_t)r * 32 + lane];
    float* dst = out + (size_t)c * HC + lane * 4;
    atomicAdd(dst + 0, v.x * w);
    atomicAdd(dst + 1, v.y * w);
    atomicAdd(dst + 2, v.z * w);
    atomicAdd(dst + 3, v.w * w);
}

// ---------------------------------------------------------------------------
extern "C" void kernel_launch(void* const* d_in, const int* in_sizes, int n_in,
                              void* d_out, int out_size) {
    const float* x  = (const float*)d_in[0];
    const int*   ei = (const int*)d_in[1];
    const float* ct = (const float*)d_in[2];
    const float* lw = (const float*)d_in[3];
    const float* lb = (const float*)d_in[4];
    const float* as = (const float*)d_in[5];
    const float* ad = (const float*)d_in[6];
    float* out = (float*)d_out;

    k_prep<<<64, 256>>>(lw, lb, as, ad, ct);
    k_init<<<(N_NODES * HC + 255) / 256, 256>>>(out);
    k_xt<<<(N_NODES + NPB - 1) / NPB, 128>>>(x);
    k_edge_alpha<<<(N_EDGES + 255) / 256, 256>>>(ei);
    k_edge_exp<<<(N_EDGES + 255) / 256, 256>>>(ei);
    {
        long long threads = (long long)N_EDGES * 32;
        int blocks = (int)((threads + 255) / 256);
        k_agg<<<blocks, 256>>>(ei, out);
    }
}

// round 2
// speedup vs baseline: 1.4971x; 1.4971x over previous
#include <cuda_runtime.h>

#define N_NODES 50000
#define N_EDGES 600000
#define IN_CH 128
#define HC 128
#define HEADS 4
#define NEG_SLOPE 0.2f
#define NPB 32   // nodes per block in transform kernel

typedef unsigned long long ull;

// ---------------- scratch (device globals; no allocations allowed) ----------
__device__ float g_Wt[IN_CH * HC];          // W transposed: [i][o]
__device__ float g_bias[HC];
__device__ float g_asrc[HC];
__device__ float g_adst[HC];
__device__ float g_xt[(size_t)N_NODES * HC];        // 25.6 MB, L2-resident
__device__ float g_alpha_src[N_NODES * HEADS];
__device__ float g_alpha_dst[N_NODES * HEADS];
__device__ int   g_deg[N_NODES];
__device__ int   g_off[N_NODES + 1];
__device__ int   g_cursor[N_NODES];
__device__ int   g_csr_src[N_EDGES];

// ---------------- f32x2 packed-math helpers (sm_10x) -------------------------
__device__ __forceinline__ ull pk2(float a, float b) {
    ull r; asm("mov.b64 %0, {%1, %2};" : "=l"(r) : "f"(a), "f"(b)); return r;
}
__device__ __forceinline__ void upk2(ull v, float& a, float& b) {
    asm("mov.b64 {%0, %1}, %2;" : "=f"(a), "=f"(b) : "l"(v));
}
__device__ __forceinline__ ull fma2(ull a, ull b, ull c) {
    ull d; asm("fma.rn.f32x2 %0, %1, %2, %3;" : "=l"(d) : "l"(a), "l"(b), "l"(c)); return d;
}
__device__ __forceinline__ ull mul2(ull a, ull b) {
    ull d; asm("mul.rn.f32x2 %0, %1, %2;" : "=l"(d) : "l"(a), "l"(b)); return d;
}
__device__ __forceinline__ ull add2(ull a, ull b) {
    ull d; asm("add.rn.f32x2 %0, %1, %2;" : "=l"(d) : "l"(a), "l"(b)); return d;
}

// ---------------- kernel 1: Bezier param interpolation + zero deg -----------
__global__ void k_prep(const float* __restrict__ lw, const float* __restrict__ lb,
                       const float* __restrict__ as, const float* __restrict__ ad,
                       const float* __restrict__ ct) {
    float c0 = ct[0], c1 = ct[1], c2 = ct[2];
    for (int idx = blockIdx.x * blockDim.x + threadIdx.x; idx < N_NODES;
         idx += gridDim.x * blockDim.x) {
        if (idx < IN_CH * HC) {
            int i = idx / HC;
            int o = idx % HC;
            g_Wt[idx] = c0 * lw[o * IN_CH + i]
                      + c1 * lw[IN_CH * HC + o * IN_CH + i]
                      + c2 * lw[2 * IN_CH * HC + o * IN_CH + i];
        }
        if (idx < HC) {
            g_bias[idx] = c0 * lb[idx] + c1 * lb[HC + idx] + c2 * lb[2 * HC + idx];
            g_asrc[idx] = c0 * as[idx] + c1 * as[HC + idx] + c2 * as[2 * HC + idx];
            g_adst[idx] = c0 * ad[idx] + c1 * ad[HC + idx] + c2 * ad[2 * HC + idx];
        }
        g_deg[idx] = 0;
    }
}

// ---------------- kernel 2: degree count ------------------------------------
__global__ void k_count(const int* __restrict__ ei) {
    int e = blockIdx.x * blockDim.x + threadIdx.x;
    if (e >= N_EDGES) return;
    atomicAdd(&g_deg[ei[N_EDGES + e]], 1);
}

// ---------------- kernel 3: single-block exclusive scan ---------------------
#define SCAN_T 1024
#define SCAN_CH 49   // 1024*49 = 50176 >= 50000
__global__ void __launch_bounds__(SCAN_T) k_scan() {
    __shared__ int part[SCAN_T];
    int tid = threadIdx.x;
    int s0 = tid * SCAN_CH;
    int sum = 0;
    for (int i = 0; i < SCAN_CH; i++) {
        int n = s0 + i;
        if (n < N_NODES) sum += g_deg[n];
    }
    part[tid] = sum;
    __syncthreads();
    for (int d = 1; d < SCAN_T; d <<= 1) {
        int v = 0;
        if (tid >= d) v = part[tid - d];
        __syncthreads();
        part[tid] += v;
        __syncthreads();
    }
    int run = (tid > 0) ? part[tid - 1] : 0;  // exclusive prefix for this chunk
    for (int i = 0; i < SCAN_CH; i++) {
        int n = s0 + i;
        if (n < N_NODES) {
            g_off[n] = run;
            g_cursor[n] = run;
            run += g_deg[n];
        }
    }
    if (tid == SCAN_T - 1) g_off[N_NODES] = part[SCAN_T - 1];
}

// ---------------- kernel 4: scatter edges into CSR (by target node) ---------
__global__ void k_scatter(const int* __restrict__ ei) {
    int e = blockIdx.x * blockDim.x + threadIdx.x;
    if (e >= N_EDGES) return;
    int r = ei[e];
    int c = ei[N_EDGES + e];
    int pos = atomicAdd(&g_cursor[c], 1);
    g_csr_src[pos] = r;
}

// ---------------- kernel 5: node transform (f32x2 packed GEMM) --------------
// Block = 32 nodes (16 node-pairs packed lo/hi), 128 threads, thread t owns
// output column t. x tile in smem as float2 pairs; LDS.128 fetches 2 i-steps
// for a node-pair -> 1 LDS per 2 FMA2 (4 MACs). fma pipe bound.
__global__ void __launch_bounds__(128) k_xt(const float* __restrict__ x) {
    __shared__ float2 xsp[16][IN_CH];   // [pair][i] = {x[n0+p][i], x[n0+p+16][i]}
    int n0 = blockIdx.x * NPB;
    int t = threadIdx.x;

    #pragma unroll
    for (int p = 0; p < 16; p++) {
        int na = n0 + p, nb = n0 + p + 16;
        float2 f;
        f.x = (na < N_NODES) ? x[(size_t)na * IN_CH + t] : 0.0f;
        f.y = (nb < N_NODES) ? x[(size_t)nb * IN_CH + t] : 0.0f;
        xsp[p][t] = f;
    }
    __syncthreads();

    ull acc[16];
    float b = g_bias[t];
    ull b2 = pk2(b, b);
    #pragma unroll
    for (int p = 0; p < 16; p++) acc[p] = b2;

    #pragma unroll 2
    for (int i = 0; i < IN_CH; i += 2) {
        float w0 = g_Wt[i * HC + t];
        float w1 = g_Wt[(i + 1) * HC + t];
        ull w02 = pk2(w0, w0);
        ull w12 = pk2(w1, w1);
        #pragma unroll
        for (int p = 0; p < 16; p++) {
            longlong2 xv = *reinterpret_cast<const longlong2*>(&xsp[p][i]);
            acc[p] = fma2((ull)xv.x, w02, acc[p]);
            acc[p] = fma2((ull)xv.y, w12, acc[p]);
        }
    }

    // write xt + attention dot products (warp h covers head h channels)
    int h = t >> 5;
    float a_s = g_asrc[t];
    float a_d = g_adst[t];
    ull as2 = pk2(a_s, a_s);
    ull ad2 = pk2(a_d, a_d);

    #pragma unroll
    for (int p = 0; p < 16; p++) {
        int na = n0 + p, nb = n0 + p + 16;
        float lo, hi;
        upk2(acc[p], lo, hi);
        if (na < N_NODES) g_xt[(size_t)na * HC + t] = lo;
        if (nb < N_NODES) g_xt[(size_t)nb * HC + t] = hi;

        ull vs = mul2(acc[p], as2);
        ull vd = mul2(acc[p], ad2);
        #pragma unroll
        for (int off = 16; off > 0; off >>= 1) {
            vs = add2(vs, __shfl_xor_sync(0xffffffffu, vs, off));
            vd = add2(vd, __shfl_xor_sync(0xffffffffu, vd, off));
        }
        if ((t & 31) == 0) {
            float vsl, vsh, vdl, vdh;
            upk2(vs, vsl, vsh);
            upk2(vd, vdl, vdh);
            if (na < N_NODES) {
                g_alpha_src[na * HEADS + h] = vsl;
                g_alpha_dst[na * HEADS + h] = vdl;
            }
            if (nb < N_NODES) {
                g_alpha_src[nb * HEADS + h] = vsh;
                g_alpha_dst[nb * HEADS + h] = vdh;
            }
        }
    }
}

// ---------------- kernel 6: fused softmax + aggregation (warp per node) -----
// Pass 1: segment max (recompute alpha, cheap). Pass 2: exp, denom, and
// weighted accumulate of xt[src] into registers. One coalesced write to out.
// No atomics anywhere.
__global__ void k_node(float* __restrict__ out) {
    int gw = (int)(((long long)blockIdx.x * blockDim.x + threadIdx.x) >> 5);
    if (gw >= N_NODES) return;
    int lane = threadIdx.x & 31;
    int h = lane >> 3;
    int base = g_off[gw];
    int end = g_off[gw + 1];
    float ad = g_alpha_dst[gw * HEADS + h];

    float m = -1e30f;
    for (int e = base; e < end; e++) {
        int s = __ldg(&g_csr_src[e]);
        float a = __ldg(&g_alpha_src[s * HEADS + h]) + ad;
        a = (a > 0.0f) ? a : NEG_SLOPE * a;
        m = fmaxf(m, a);
    }

    float4 acc = make_float4(0.f, 0.f, 0.f, 0.f);
    float denom = 0.0f;
    for (int e = base; e < end; e++) {
        int s = __ldg(&g_csr_src[e]);
        float a = __ldg(&g_alpha_src[s * HEADS + h]) + ad;
        a = (a > 0.0f) ? a : NEG_SLOPE * a;
        float ex = __expf(a - m);
        denom += ex;
        float4 v = __ldg(&((const float4*)g_xt)[(size_t)s * 32 + lane]);
        acc.x += v.x * ex;
        acc.y += v.y * ex;
        acc.z += v.z * ex;
        acc.w += v.w * ex;
    }
    float inv = 1.0f / (denom + 1e-16f);
    float4 o = make_float4(acc.x * inv, acc.y * inv, acc.z * inv, acc.w * inv);
    ((float4*)out)[(size_t)gw * 32 + lane] = o;
}

// ---------------------------------------------------------------------------
extern "C" void kernel_launch(void* const* d_in, const int* in_sizes, int n_in,
                              void* d_out, int out_size) {
    const float* x  = (const float*)d_in[0];
    const int*   ei = (const int*)d_in[1];
    const float* ct = (const float*)d_in[2];
    const float* lw = (const float*)d_in[3];
    const float* lb = (const float*)d_in[4];
    const float* as = (const float*)d_in[5];
    const float* ad = (const float*)d_in[6];
    float* out = (float*)d_out;

    k_prep<<<(N_NODES + 255) / 256, 256>>>(lw, lb, as, ad, ct);
    k_count<<<(N_EDGES + 255) / 256, 256>>>(ei);
    k_scan<<<1, SCAN_T>>>();
    k_scatter<<<(N_EDGES + 255) / 256, 256>>>(ei);
    k_xt<<<(N_NODES + NPB - 1) / NPB, 128>>>(x);
    {
        long long threads = (long long)N_NODES * 32;
        int blocks = (int)((threads + 255) / 256);
        k_node<<<blocks, 256>>>(out);
    }
}

// round 3
// speedup vs baseline: 2.1894x; 1.4624x over previous
#include <cuda_runtime.h>

#define N_NODES 50000
#define N_EDGES 600000
#define IN_CH 128
#define HC 128
#define HEADS 4
#define NEG_SLOPE 0.2f
#define NPB 32
#define NBLK_A 196   // ceil(50000/256)

typedef unsigned long long ull;

// ---------------- scratch (device globals) -----------------------------------
__device__ float g_Wt[IN_CH * HC];
__device__ float g_bias[HC];
__device__ float g_asrc[HC];
__device__ float g_adst[HC];
__device__ float g_xt[(size_t)N_NODES * HC];
__device__ float g_alpha_src[N_NODES * HEADS];
__device__ float g_alpha_dst[N_NODES * HEADS];
__device__ int   g_deg[N_NODES];
__device__ int   g_tmp[N_NODES];      // block-local exclusive scan
__device__ int   g_bsum[NBLK_A];      // per-block totals
__device__ int   g_boff[NBLK_A];      // block prefix
__device__ int   g_off[N_NODES + 1];
__device__ int   g_cursor[N_NODES];
__device__ int   g_csr_src[N_EDGES];

// ---------------- f32x2 packed-math helpers -----------------------------------
__device__ __forceinline__ ull pk2(float a, float b) {
    ull r; asm("mov.b64 %0, {%1, %2};" : "=l"(r) : "f"(a), "f"(b)); return r;
}
__device__ __forceinline__ void upk2(ull v, float& a, float& b) {
    asm("mov.b64 {%0, %1}, %2;" : "=f"(a), "=f"(b) : "l"(v));
}
__device__ __forceinline__ ull fma2(ull a, ull b, ull c) {
    ull d; asm("fma.rn.f32x2 %0, %1, %2, %3;" : "=l"(d) : "l"(a), "l"(b), "l"(c)); return d;
}
__device__ __forceinline__ ull mul2(ull a, ull b) {
    ull d; asm("mul.rn.f32x2 %0, %1, %2;" : "=l"(d) : "l"(a), "l"(b)); return d;
}
__device__ __forceinline__ ull add2(ull a, ull b) {
    ull d; asm("add.rn.f32x2 %0, %1, %2;" : "=l"(d) : "l"(a), "l"(b)); return d;
}

// ---------------- kernel 1: Bezier param interpolation + zero deg ------------
__global__ void k_prep(const float* __restrict__ lw, const float* __restrict__ lb,
                       const float* __restrict__ as, const float* __restrict__ ad,
                       const float* __restrict__ ct) {
    float c0 = ct[0], c1 = ct[1], c2 = ct[2];
    for (int idx = blockIdx.x * blockDim.x + threadIdx.x; idx < N_NODES;
         idx += gridDim.x * blockDim.x) {
        if (idx < IN_CH * HC) {
            int i = idx / HC;
            int o = idx % HC;
            g_Wt[idx] = c0 * lw[o * IN_CH + i]
                      + c1 * lw[IN_CH * HC + o * IN_CH + i]
                      + c2 * lw[2 * IN_CH * HC + o * IN_CH + i];
        }
        if (idx < HC) {
            g_bias[idx] = c0 * lb[idx] + c1 * lb[HC + idx] + c2 * lb[2 * HC + idx];
            g_asrc[idx] = c0 * as[idx] + c1 * as[HC + idx] + c2 * as[2 * HC + idx];
            g_adst[idx] = c0 * ad[idx] + c1 * ad[HC + idx] + c2 * ad[2 * HC + idx];
        }
        g_deg[idx] = 0;
    }
}

// ---------------- kernel 2: degree count --------------------------------------
__global__ void k_count(const int* __restrict__ ei) {
    int e = blockIdx.x * blockDim.x + threadIdx.x;
    if (e >= N_EDGES) return;
    atomicAdd(&g_deg[ei[N_EDGES + e]], 1);
}

// ---------------- scan phase A: per-block exclusive scan ----------------------
__global__ void __launch_bounds__(256) k_scanA() {
    int tid = threadIdx.x;
    int n = blockIdx.x * 256 + tid;
    int v = (n < N_NODES) ? g_deg[n] : 0;
    int incl = v;
    #pragma unroll
    for (int d = 1; d < 32; d <<= 1) {
        int t = __shfl_up_sync(0xffffffffu, incl, d);
        if ((tid & 31) >= d) incl += t;
    }
    __shared__ int wsum[8];
    if ((tid & 31) == 31) wsum[tid >> 5] = incl;
    __syncthreads();
    if (tid < 8) {
        int s = wsum[tid];
        #pragma unroll
        for (int d = 1; d < 8; d <<= 1) {
            int t = __shfl_up_sync(0xffu, s, d);
            if (tid >= d) s += t;
        }
        wsum[tid] = s;
    }
    __syncthreads();
    int wid = tid >> 5;
    int excl = (wid > 0 ? wsum[wid - 1] : 0) + incl - v;
    if (n < N_NODES) g_tmp[n] = excl;
    if (tid == 255) g_bsum[blockIdx.x] = wsum[7];
}

// ---------------- scan phase B: scan of block sums (1 block) ------------------
__global__ void __launch_bounds__(256) k_scanB() {
    int tid = threadIdx.x;
    int v = (tid < NBLK_A) ? g_bsum[tid] : 0;
    int incl = v;
    #pragma unroll
    for (int d = 1; d < 32; d <<= 1) {
        int t = __shfl_up_sync(0xffffffffu, incl, d);
        if ((tid & 31) >= d) incl += t;
    }
    __shared__ int wsum[8];
    if ((tid & 31) == 31) wsum[tid >> 5] = incl;
    __syncthreads();
    if (tid < 8) {
        int s = wsum[tid];
        #pragma unroll
        for (int d = 1; d < 8; d <<= 1) {
            int t = __shfl_up_sync(0xffu, s, d);
            if (tid >= d) s += t;
        }
        wsum[tid] = s;
    }
    __syncthreads();
    int wid = tid >> 5;
    int excl = (wid > 0 ? wsum[wid - 1] : 0) + incl - v;
    if (tid < NBLK_A) g_boff[tid] = excl;
    if (tid == 255) g_off[N_NODES] = wsum[7];   // total == N_EDGES
}

// ---------------- scan phase C: combine + init cursor -------------------------
__global__ void k_scanC() {
    int n = blockIdx.x * blockDim.x + threadIdx.x;
    if (n >= N_NODES) return;
    int off = g_boff[n >> 8] + g_tmp[n];
    g_off[n] = off;
    g_cursor[n] = off;
}

// ---------------- kernel: scatter edges into CSR (by target) ------------------
__global__ void k_scatter(const int* __restrict__ ei) {
    int e = blockIdx.x * blockDim.x + threadIdx.x;
    if (e >= N_EDGES) return;
    int r = ei[e];
    int c = ei[N_EDGES + e];
    int pos = atomicAdd(&g_cursor[c], 1);
    g_csr_src[pos] = r;
}

// ---------------- kernel: node transform (f32x2 packed GEMM) ------------------
__global__ void __launch_bounds__(128) k_xt(const float* __restrict__ x) {
    __shared__ float2 xsp[16][IN_CH];
    int n0 = blockIdx.x * NPB;
    int t = threadIdx.x;

    #pragma unroll
    for (int p = 0; p < 16; p++) {
        int na = n0 + p, nb = n0 + p + 16;
        float2 f;
        f.x = (na < N_NODES) ? x[(size_t)na * IN_CH + t] : 0.0f;
        f.y = (nb < N_NODES) ? x[(size_t)nb * IN_CH + t] : 0.0f;
        xsp[p][t] = f;
    }
    __syncthreads();

    ull acc[16];
    float b = g_bias[t];
    ull b2 = pk2(b, b);
    #pragma unroll
    for (int p = 0; p < 16; p++) acc[p] = b2;

    #pragma unroll 2
    for (int i = 0; i < IN_CH; i += 2) {
        float w0 = g_Wt[i * HC + t];
        float w1 = g_Wt[(i + 1) * HC + t];
        ull w02 = pk2(w0, w0);
        ull w12 = pk2(w1, w1);
        #pragma unroll
        for (int p = 0; p < 16; p++) {
            longlong2 xv = *reinterpret_cast<const longlong2*>(&xsp[p][i]);
            acc[p] = fma2((ull)xv.x, w02, acc[p]);
            acc[p] = fma2((ull)xv.y, w12, acc[p]);
        }
    }

    int h = t >> 5;
    float a_s = g_asrc[t];
    float a_d = g_adst[t];
    ull as2 = pk2(a_s, a_s);
    ull ad2 = pk2(a_d, a_d);

    #pragma unroll
    for (int p = 0; p < 16; p++) {
        int na = n0 + p, nb = n0 + p + 16;
        float lo, hi;
        upk2(acc[p], lo, hi);
        if (na < N_NODES) g_xt[(size_t)na * HC + t] = lo;
        if (nb < N_NODES) g_xt[(size_t)nb * HC + t] = hi;

        ull vs = mul2(acc[p], as2);
        ull vd = mul2(acc[p], ad2);
        #pragma unroll
        for (int off = 16; off > 0; off >>= 1) {
            vs = add2(vs, __shfl_xor_sync(0xffffffffu, vs, off));
            vd = add2(vd, __shfl_xor_sync(0xffffffffu, vd, off));
        }
        if ((t & 31) == 0) {
            float vsl, vsh, vdl, vdh;
            upk2(vs, vsl, vsh);
            upk2(vd, vdl, vdh);
            if (na < N_NODES) {
                g_alpha_src[na * HEADS + h] = vsl;
                g_alpha_dst[na * HEADS + h] = vdl;
            }
            if (nb < N_NODES) {
                g_alpha_src[nb * HEADS + h] = vsh;
                g_alpha_dst[nb * HEADS + h] = vdh;
            }
        }
    }
}

// ---------------- kernel: fused ONLINE softmax + aggregation (warp/node) ------
// Single pass: running max with exp-rescale. No atomics, one coalesced write.
__global__ void k_node(float* __restrict__ out) {
    int gw = (int)(((long long)blockIdx.x * blockDim.x + threadIdx.x) >> 5);
    if (gw >= N_NODES) return;
    int lane = threadIdx.x & 31;
    int h = lane >> 3;
    int base = g_off[gw];
    int end = g_off[gw + 1];
    float ad = g_alpha_dst[gw * HEADS + h];

    float m = -1e30f;
    float denom = 0.0f;
    float4 acc = make_float4(0.f, 0.f, 0.f, 0.f);

    for (int e = base; e < end; e++) {
        int s = __ldg(&g_csr_src[e]);
        float a = __ldg(&g_alpha_src[s * HEADS + h]) + ad;
        a = (a > 0.0f) ? a : NEG_SLOPE * a;
        if (a > m) {
            float sc = __expf(m - a);   // 0 on first edge (m=-1e30)
            denom *= sc;
            acc.x *= sc; acc.y *= sc; acc.z *= sc; acc.w *= sc;
            m = a;
        }
        float ex = __expf(a - m);
        denom += ex;
        float4 v = __ldg(&((const float4*)g_xt)[(size_t)s * 32 + lane]);
        acc.x += v.x * ex;
        acc.y += v.y * ex;
        acc.z += v.z * ex;
        acc.w += v.w * ex;
    }
    float inv = 1.0f / (denom + 1e-16f);
    float4 o = make_float4(acc.x * inv, acc.y * inv, acc.z * inv, acc.w * inv);
    ((float4*)out)[(size_t)gw * 32 + lane] = o;
}

// ---------------------------------------------------------------------------
extern "C" void kernel_launch(void* const* d_in, const int* in_sizes, int n_in,
                              void* d_out, int out_size) {
    const float* x  = (const float*)d_in[0];
    const int*   ei = (const int*)d_in[1];
    const float* ct = (const float*)d_in[2];
    const float* lw = (const float*)d_in[3];
    const float* lb = (const float*)d_in[4];
    const float* as = (const float*)d_in[5];
    const float* ad = (const float*)d_in[6];
    float* out = (float*)d_out;

    k_prep<<<(N_NODES + 255) / 256, 256>>>(lw, lb, as, ad, ct);
    k_count<<<(N_EDGES + 255) / 256, 256>>>(ei);
    k_scanA<<<NBLK_A, 256>>>();
    k_scanB<<<1, 256>>>();
    k_scanC<<<(N_NODES + 255) / 256, 256>>>();
    k_scatter<<<(N_EDGES + 255) / 256, 256>>>(ei);
    k_xt<<<(N_NODES + NPB - 1) / NPB, 128>>>(x);
    {
        long long threads = (long long)N_NODES * 32;
        int blocks = (int)((threads + 255) / 256);
        k_node<<<blocks, 256>>>(out);
    }
}

// round 4
// speedup vs baseline: 2.1928x; 1.0015x over previous
#include <cuda_runtime.h>

#define N_NODES 50000
#define N_EDGES 600000
#define IN_CH 128
#define HC 128
#define HEADS 4
#define NEG_SLOPE 0.2f
#define NPB 32
#define NBLK_A 196   // ceil(50000/256)

typedef unsigned long long ull;

// ---------------- scratch (device globals) -----------------------------------
__device__ float g_Wt[IN_CH * HC];
__device__ float g_bias[HC];
__device__ float g_asrc[HC];
__device__ float g_adst[HC];
__device__ float g_xt[(size_t)N_NODES * HC];
__device__ float g_alpha_src[N_NODES * HEADS];
__device__ float g_alpha_dst[N_NODES * HEADS];
__device__ int   g_deg[N_NODES];
__device__ int   g_tmp[N_NODES];       // block-local exclusive scan
__device__ int   g_bsum[NBLK_A];       // per-block totals
__device__ int   g_boff[NBLK_A];       // block prefix
__device__ int   g_done;               // ticket for last-block scan
__device__ int   g_off[N_NODES + 1];
__device__ int   g_cursor[N_NODES];
__device__ int   g_csr_src[N_EDGES];
__device__ float g_csr_alpha[(size_t)N_EDGES * 4];  // leaky(as[r]+ad[c]) per head

// ---------------- f32x2 packed-math helpers -----------------------------------
__device__ __forceinline__ ull pk2(float a, float b) {
    ull r; asm("mov.b64 %0, {%1, %2};" : "=l"(r) : "f"(a), "f"(b)); return r;
}
__device__ __forceinline__ void upk2(ull v, float& a, float& b) {
    asm("mov.b64 {%0, %1}, %2;" : "=f"(a), "=f"(b) : "l"(v));
}
__device__ __forceinline__ ull fma2(ull a, ull b, ull c) {
    ull d; asm("fma.rn.f32x2 %0, %1, %2, %3;" : "=l"(d) : "l"(a), "l"(b), "l"(c)); return d;
}
__device__ __forceinline__ ull mul2(ull a, ull b) {
    ull d; asm("mul.rn.f32x2 %0, %1, %2;" : "=l"(d) : "l"(a), "l"(b)); return d;
}
__device__ __forceinline__ ull add2(ull a, ull b) {
    ull d; asm("add.rn.f32x2 %0, %1, %2;" : "=l"(d) : "l"(a), "l"(b)); return d;
}

// ---------------- kernel 1: Bezier param interpolation + init ------------------
__global__ void k_prep(const float* __restrict__ lw, const float* __restrict__ lb,
                       const float* __restrict__ as, const float* __restrict__ ad,
                       const float* __restrict__ ct) {
    float c0 = ct[0], c1 = ct[1], c2 = ct[2];
    int idx0 = blockIdx.x * blockDim.x + threadIdx.x;
    for (int idx = idx0; idx < N_NODES; idx += gridDim.x * blockDim.x) {
        if (idx < IN_CH * HC) {
            int i = idx / HC;
            int o = idx % HC;
            g_Wt[idx] = c0 * lw[o * IN_CH + i]
                      + c1 * lw[IN_CH * HC + o * IN_CH + i]
                      + c2 * lw[2 * IN_CH * HC + o * IN_CH + i];
        }
        if (idx < HC) {
            g_bias[idx] = c0 * lb[idx] + c1 * lb[HC + idx] + c2 * lb[2 * HC + idx];
            g_asrc[idx] = c0 * as[idx] + c1 * as[HC + idx] + c2 * as[2 * HC + idx];
            g_adst[idx] = c0 * ad[idx] + c1 * ad[HC + idx] + c2 * ad[2 * HC + idx];
        }
        g_deg[idx] = 0;
    }
    if (idx0 == 0) {
        g_done = 0;
        g_off[N_NODES] = N_EDGES;
    }
}

// ---------------- kernel 2: degree count --------------------------------------
__global__ void k_count(const int* __restrict__ ei) {
    int e = blockIdx.x * blockDim.x + threadIdx.x;
    if (e >= N_EDGES) return;
    atomicAdd(&g_deg[ei[N_EDGES + e]], 1);
}

// ---------------- scan phase A: per-block scan + last-block global scan -------
__global__ void __launch_bounds__(256) k_scanA() {
    int tid = threadIdx.x;
    int n = blockIdx.x * 256 + tid;
    int v = (n < N_NODES) ? g_deg[n] : 0;
    int incl = v;
    #pragma unroll
    for (int d = 1; d < 32; d <<= 1) {
        int t = __shfl_up_sync(0xffffffffu, incl, d);
        if ((tid & 31) >= d) incl += t;
    }
    __shared__ int wsum[8];
    if ((tid & 31) == 31) wsum[tid >> 5] = incl;
    __syncthreads();
    if (tid < 8) {
        int s = wsum[tid];
        #pragma unroll
        for (int d = 1; d < 8; d <<= 1) {
            int t = __shfl_up_sync(0xffu, s, d);
            if (tid >= d) s += t;
        }
        wsum[tid] = s;
    }
    __syncthreads();
    int wid = tid >> 5;
    int excl = (wid > 0 ? wsum[wid - 1] : 0) + incl - v;
    if (n < N_NODES) g_tmp[n] = excl;

    // publish block sum; last block to finish scans the 196 block sums
    __shared__ int amLast;
    if (tid == 0) {
        g_bsum[blockIdx.x] = wsum[7];
        __threadfence();
        int t = atomicAdd(&g_done, 1);
        amLast = (t == NBLK_A - 1);
    }
    __syncthreads();
    if (amLast) {
        __threadfence();
        int bv = (tid < NBLK_A) ? g_bsum[tid] : 0;
        int binc = bv;
        #pragma unroll
        for (int d = 1; d < 32; d <<= 1) {
            int t = __shfl_up_sync(0xffffffffu, binc, d);
            if ((tid & 31) >= d) binc += t;
        }
        if ((tid & 31) == 31) wsum[tid >> 5] = binc;
        __syncthreads();
        if (tid < 8) {
            int s = wsum[tid];
            #pragma unroll
            for (int d = 1; d < 8; d <<= 1) {
                int t = __shfl_up_sync(0xffu, s, d);
                if (tid >= d) s += t;
            }
            wsum[tid] = s;
        }
        __syncthreads();
        int bexcl = ((tid >> 5) > 0 ? wsum[(tid >> 5) - 1] : 0) + binc - bv;
        if (tid < NBLK_A) g_boff[tid] = bexcl;
    }
}

// ---------------- scan phase C: combine + init cursor -------------------------
__global__ void k_scanC() {
    int n = blockIdx.x * blockDim.x + threadIdx.x;
    if (n >= N_NODES) return;
    int off = g_boff[n >> 8] + g_tmp[n];
    g_off[n] = off;
    g_cursor[n] = off;
}

// ---------------- kernel: node transform (f32x2 packed GEMM) ------------------
__global__ void __launch_bounds__(128) k_xt(const float* __restrict__ x) {
    __shared__ float2 xsp[16][IN_CH];
    int n0 = blockIdx.x * NPB;
    int t = threadIdx.x;

    #pragma unroll
    for (int p = 0; p < 16; p++) {
        int na = n0 + p, nb = n0 + p + 16;
        float2 f;
        f.x = (na < N_NODES) ? x[(size_t)na * IN_CH + t] : 0.0f;
        f.y = (nb < N_NODES) ? x[(size_t)nb * IN_CH + t] : 0.0f;
        xsp[p][t] = f;
    }
    __syncthreads();

    ull acc[16];
    float b = g_bias[t];
    ull b2 = pk2(b, b);
    #pragma unroll
    for (int p = 0; p < 16; p++) acc[p] = b2;

    #pragma unroll 2
    for (int i = 0; i < IN_CH; i += 2) {
        float w0 = g_Wt[i * HC + t];
        float w1 = g_Wt[(i + 1) * HC + t];
        ull w02 = pk2(w0, w0);
        ull w12 = pk2(w1, w1);
        #pragma unroll
        for (int p = 0; p < 16; p++) {
            longlong2 xv = *reinterpret_cast<const longlong2*>(&xsp[p][i]);
            acc[p] = fma2((ull)xv.x, w02, acc[p]);
            acc[p] = fma2((ull)xv.y, w12, acc[p]);
        }
    }

    int h = t >> 5;
    float a_s = g_asrc[t];
    float a_d = g_adst[t];
    ull as2 = pk2(a_s, a_s);
    ull ad2 = pk2(a_d, a_d);

    #pragma unroll
    for (int p = 0; p < 16; p++) {
        int na = n0 + p, nb = n0 + p + 16;
        float lo, hi;
        upk2(acc[p], lo, hi);
        if (na < N_NODES) g_xt[(size_t)na * HC + t] = lo;
        if (nb < N_NODES) g_xt[(size_t)nb * HC + t] = hi;

        ull vs = mul2(acc[p], as2);
        ull vd = mul2(acc[p], ad2);
        #pragma unroll
        for (int off = 16; off > 0; off >>= 1) {
            vs = add2(vs, __shfl_xor_sync(0xffffffffu, vs, off));
            vd = add2(vd, __shfl_xor_sync(0xffffffffu, vd, off));
        }
        if ((t & 31) == 0) {
            float vsl, vsh, vdl, vdh;
            upk2(vs, vsl, vsh);
            upk2(vd, vdl, vdh);
            if (na < N_NODES) {
                g_alpha_src[na * HEADS + h] = vsl;
                g_alpha_dst[na * HEADS + h] = vdl;
            }
            if (nb < N_NODES) {
                g_alpha_src[nb * HEADS + h] = vsh;
                g_alpha_dst[nb * HEADS + h] = vdh;
            }
        }
    }
}

// ---------------- kernel: scatter + edge attention (fused) --------------------
// Builds CSR and precomputes leaky(alpha_src[r]+alpha_dst[c]) so k_node's
// inner loop has no dependent alpha gathers.
__global__ void k_scatter(const int* __restrict__ ei) {
    int e = blockIdx.x * blockDim.x + threadIdx.x;
    if (e >= N_EDGES) return;
    int r = ei[e];
    int c = ei[N_EDGES + e];
    float4 as = __ldg(&((const float4*)g_alpha_src)[r]);
    float4 ad = __ldg(&((const float4*)g_alpha_dst)[c]);
    float4 a;
    a.x = as.x + ad.x; a.x = (a.x > 0.f) ? a.x : NEG_SLOPE * a.x;
    a.y = as.y + ad.y; a.y = (a.y > 0.f) ? a.y : NEG_SLOPE * a.y;
    a.z = as.z + ad.z; a.z = (a.z > 0.f) ? a.z : NEG_SLOPE * a.z;
    a.w = as.w + ad.w; a.w = (a.w > 0.f) ? a.w : NEG_SLOPE * a.w;
    int pos = atomicAdd(&g_cursor[c], 1);
    g_csr_src[pos] = r;
    ((float4*)g_csr_alpha)[pos] = a;
}

// ---------------- kernel: fused online softmax + aggregation (warp/node) ------
// Branch-free online softmax; only dependent load is the xt gather.
__global__ void k_node(float* __restrict__ out) {
    int gw = (int)(((long long)blockIdx.x * blockDim.x + threadIdx.x) >> 5);
    if (gw >= N_NODES) return;
    int lane = threadIdx.x & 31;
    int h = lane >> 3;
    int base = g_off[gw];
    int end = g_off[gw + 1];

    float m = -1e30f;
    float denom = 0.0f;
    float4 acc = make_float4(0.f, 0.f, 0.f, 0.f);

    #pragma unroll 2
    for (int e = base; e < end; e++) {
        int s = __ldg(&g_csr_src[e]);
        float a = __ldg(&g_csr_alpha[(size_t)e * 4 + h]);
        float4 v = __ldg(&((const float4*)g_xt)[(size_t)s * 32 + lane]);
        float mnew = fmaxf(m, a);
        float sc = __expf(m - mnew);   // 1 if a<=m; 0 on first edge
        float ex = __expf(a - mnew);
        m = mnew;
        denom = fmaf(denom, sc, ex);
        acc.x = fmaf(v.x, ex, acc.x * sc);
        acc.y = fmaf(v.y, ex, acc.y * sc);
        acc.z = fmaf(v.z, ex, acc.z * sc);
        acc.w = fmaf(v.w, ex, acc.w * sc);
    }
    float inv = 1.0f / (denom + 1e-16f);
    float4 o = make_float4(acc.x * inv, acc.y * inv, acc.z * inv, acc.w * inv);
    ((float4*)out)[(size_t)gw * 32 + lane] = o;
}

// ---------------------------------------------------------------------------
extern "C" void kernel_launch(void* const* d_in, const int* in_sizes, int n_in,
                              void* d_out, int out_size) {
    const float* x  = (const float*)d_in[0];
    const int*   ei = (const int*)d_in[1];
    const float* ct = (const float*)d_in[2];
    const float* lw = (const float*)d_in[3];
    const float* lb = (const float*)d_in[4];
    const float* as = (const float*)d_in[5];
    const float* ad = (const float*)d_in[6];
    float* out = (float*)d_out;

    k_prep<<<(N_NODES + 255) / 256, 256>>>(lw, lb, as, ad, ct);
    k_count<<<(N_EDGES + 255) / 256, 256>>>(ei);
    k_scanA<<<NBLK_A, 256>>>();
    k_scanC<<<(N_NODES + 255) / 256, 256>>>();
    k_xt<<<(N_NODES + NPB - 1) / NPB, 128>>>(x);
    k_scatter<<<(N_EDGES + 255) / 256, 256>>>(ei);
    {
        long long threads = (long long)N_NODES * 32;
        int blocks = (int)((threads + 255) / 256);
        k_node<<<blocks, 256>>>(out);
    }
}

// round 5
// speedup vs baseline: 2.6019x; 1.1866x over previous
#include <cuda_runtime.h>

#define N_NODES 50000
#define N_EDGES 600000
#define IN_CH 128
#define HC 128
#define HEADS 4
#define NEG_SLOPE 0.2f
#define NPB 32
#define NBLK_X 1563   // ceil(50000/32); also covers edges: 1563*384 >= 600000
#define NBLK_A 196    // ceil(50000/256)

typedef unsigned long long ull;

// ---------------- scratch (device globals) -----------------------------------
__device__ float g_Wt[IN_CH * HC];
__device__ float g_bias[HC];
__device__ float g_asrc[HC];
__device__ float g_adst[HC];
__device__ float g_xt[(size_t)N_NODES * HC];
__device__ float g_alpha_src[N_NODES * HEADS];
__device__ float g_alpha_dst[N_NODES * HEADS];
__device__ int   g_deg[N_NODES];      // zeroed by k_node at end (self-reset)
__device__ int   g_cnt[N_NODES];      // scatter cursor, self-reset by k_node
__device__ int   g_tmp[N_NODES];      // block-local exclusive scan
__device__ int   g_bsum[NBLK_A];
__device__ int   g_boff[NBLK_A];
__device__ int   g_done;              // ticket, self-reset by scanA last block
__device__ int   g_csr_src[N_EDGES];
__device__ float g_csr_alpha[(size_t)N_EDGES * 4];

// ---------------- f32x2 packed-math helpers -----------------------------------
__device__ __forceinline__ ull pk2(float a, float b) {
    ull r; asm("mov.b64 %0, {%1, %2};" : "=l"(r) : "f"(a), "f"(b)); return r;
}
__device__ __forceinline__ void upk2(ull v, float& a, float& b) {
    asm("mov.b64 {%0, %1}, %2;" : "=f"(a), "=f"(b) : "l"(v));
}
__device__ __forceinline__ ull fma2(ull a, ull b, ull c) {
    ull d; asm("fma.rn.f32x2 %0, %1, %2, %3;" : "=l"(d) : "l"(a), "l"(b), "l"(c)); return d;
}
__device__ __forceinline__ ull mul2(ull a, ull b) {
    ull d; asm("mul.rn.f32x2 %0, %1, %2;" : "=l"(d) : "l"(a), "l"(b)); return d;
}
__device__ __forceinline__ ull add2(ull a, ull b) {
    ull d; asm("add.rn.f32x2 %0, %1, %2;" : "=l"(d) : "l"(a), "l"(b)); return d;
}

// ---------------- kernel 1: Bezier param interpolation -------------------------
__global__ void k_prep(const float* __restrict__ lw, const float* __restrict__ lb,
                       const float* __restrict__ as, const float* __restrict__ ad,
                       const float* __restrict__ ct) {
    float c0 = ct[0], c1 = ct[1], c2 = ct[2];
    int idx = blockIdx.x * blockDim.x + threadIdx.x;   // 16384 threads
    if (idx < IN_CH * HC) {
        int i = idx / HC;
        int o = idx % HC;
        g_Wt[idx] = c0 * lw[o * IN_CH + i]
                  + c1 * lw[IN_CH * HC + o * IN_CH + i]
                  + c2 * lw[2 * IN_CH * HC + o * IN_CH + i];
    }
    if (idx < HC) {
        g_bias[idx] = c0 * lb[idx] + c1 * lb[HC + idx] + c2 * lb[2 * HC + idx];
        g_asrc[idx] = c0 * as[idx] + c1 * as[HC + idx] + c2 * as[2 * HC + idx];
        g_adst[idx] = c0 * ad[idx] + c1 * ad[HC + idx] + c2 * ad[2 * HC + idx];
    }
}

// ---------------- kernel 2: node transform (f32x2 GEMM) + fused degree count --
__global__ void __launch_bounds__(128) k_xt(const float* __restrict__ x,
                                            const int* __restrict__ ei) {
    int t = threadIdx.x;

    // fused degree count: 3 edges per thread, overlapped with GEMM load phase
    {
        int ebase = blockIdx.x * 384;
        #pragma unroll
        for (int j = 0; j < 3; j++) {
            int e = ebase + j * 128 + t;
            if (e < N_EDGES) atomicAdd(&g_deg[ei[N_EDGES + e]], 1);
        }
    }

    __shared__ float2 xsp[16][IN_CH];
    int n0 = blockIdx.x * NPB;

    #pragma unroll
    for (int p = 0; p < 16; p++) {
        int na = n0 + p, nb = n0 + p + 16;
        float2 f;
        f.x = (na < N_NODES) ? x[(size_t)na * IN_CH + t] : 0.0f;
        f.y = (nb < N_NODES) ? x[(size_t)nb * IN_CH + t] : 0.0f;
        xsp[p][t] = f;
    }
    __syncthreads();

    ull acc[16];
    float b = g_bias[t];
    ull b2 = pk2(b, b);
    #pragma unroll
    for (int p = 0; p < 16; p++) acc[p] = b2;

    #pragma unroll 2
    for (int i = 0; i < IN_CH; i += 2) {
        float w0 = g_Wt[i * HC + t];
        float w1 = g_Wt[(i + 1) * HC + t];
        ull w02 = pk2(w0, w0);
        ull w12 = pk2(w1, w1);
        #pragma unroll
        for (int p = 0; p < 16; p++) {
            longlong2 xv = *reinterpret_cast<const longlong2*>(&xsp[p][i]);
            acc[p] = fma2((ull)xv.x, w02, acc[p]);
            acc[p] = fma2((ull)xv.y, w12, acc[p]);
        }
    }

    int h = t >> 5;
    float a_s = g_asrc[t];
    float a_d = g_adst[t];
    ull as2 = pk2(a_s, a_s);
    ull ad2 = pk2(a_d, a_d);

    #pragma unroll
    for (int p = 0; p < 16; p++) {
        int na = n0 + p, nb = n0 + p + 16;
        float lo, hi;
        upk2(acc[p], lo, hi);
        if (na < N_NODES) g_xt[(size_t)na * HC + t] = lo;
        if (nb < N_NODES) g_xt[(size_t)nb * HC + t] = hi;

        ull vs = mul2(acc[p], as2);
        ull vd = mul2(acc[p], ad2);
        #pragma unroll
        for (int off = 16; off > 0; off >>= 1) {
            vs = add2(vs, __shfl_xor_sync(0xffffffffu, vs, off));
            vd = add2(vd, __shfl_xor_sync(0xffffffffu, vd, off));
        }
        if ((t & 31) == 0) {
            float vsl, vsh, vdl, vdh;
            upk2(vs, vsl, vsh);
            upk2(vd, vdl, vdh);
            if (na < N_NODES) {
                g_alpha_src[na * HEADS + h] = vsl;
                g_alpha_dst[na * HEADS + h] = vdl;
            }
            if (nb < N_NODES) {
                g_alpha_src[nb * HEADS + h] = vsh;
                g_alpha_dst[nb * HEADS + h] = vdh;
            }
        }
    }
}

// ---------------- scan: per-block scan + last-block scan of block sums --------
__global__ void __launch_bounds__(256) k_scanA() {
    int tid = threadIdx.x;
    int n = blockIdx.x * 256 + tid;
    int v = (n < N_NODES) ? g_deg[n] : 0;
    int incl = v;
    #pragma unroll
    for (int d = 1; d < 32; d <<= 1) {
        int t = __shfl_up_sync(0xffffffffu, incl, d);
        if ((tid & 31) >= d) incl += t;
    }
    __shared__ int wsum[8];
    if ((tid & 31) == 31) wsum[tid >> 5] = incl;
    __syncthreads();
    if (tid < 8) {
        int s = wsum[tid];
        #pragma unroll
        for (int d = 1; d < 8; d <<= 1) {
            int t = __shfl_up_sync(0xffu, s, d);
            if (tid >= d) s += t;
        }
        wsum[tid] = s;
    }
    __syncthreads();
    int wid = tid >> 5;
    int excl = (wid > 0 ? wsum[wid - 1] : 0) + incl - v;
    if (n < N_NODES) g_tmp[n] = excl;

    __shared__ int amLast;
    if (tid == 0) {
        g_bsum[blockIdx.x] = wsum[7];
        __threadfence();
        int t = atomicAdd(&g_done, 1);
        amLast = (t == NBLK_A - 1);
    }
    __syncthreads();
    if (amLast) {
        __threadfence();
        int bv = (tid < NBLK_A) ? g_bsum[tid] : 0;
        int binc = bv;
        #pragma unroll
        for (int d = 1; d < 32; d <<= 1) {
            int t = __shfl_up_sync(0xffffffffu, binc, d);
            if ((tid & 31) >= d) binc += t;
        }
        if ((tid & 31) == 31) wsum[tid >> 5] = binc;
        __syncthreads();
        if (tid < 8) {
            int s = wsum[tid];
            #pragma unroll
            for (int d = 1; d < 8; d <<= 1) {
                int t = __shfl_up_sync(0xffu, s, d);
                if (tid >= d) s += t;
            }
            wsum[tid] = s;
        }
        __syncthreads();
        int bexcl = ((tid >> 5) > 0 ? wsum[(tid >> 5) - 1] : 0) + binc - bv;
        if (tid < NBLK_A) g_boff[tid] = bexcl;
        if (tid == 0) g_done = 0;   // self-reset for next replay
    }
}

// ---------------- kernel: scatter + edge attention (fused) --------------------
__global__ void k_scatter(const int* __restrict__ ei) {
    int e = blockIdx.x * blockDim.x + threadIdx.x;
    if (e >= N_EDGES) return;
    int r = ei[e];
    int c = ei[N_EDGES + e];
    float4 as = __ldg(&((const float4*)g_alpha_src)[r]);
    float4 ad = __ldg(&((const float4*)g_alpha_dst)[c]);
    float4 a;
    a.x = as.x + ad.x; a.x = (a.x > 0.f) ? a.x : NEG_SLOPE * a.x;
    a.y = as.y + ad.y; a.y = (a.y > 0.f) ? a.y : NEG_SLOPE * a.y;
    a.z = as.z + ad.z; a.z = (a.z > 0.f) ? a.z : NEG_SLOPE * a.z;
    a.w = as.w + ad.w; a.w = (a.w > 0.f) ? a.w : NEG_SLOPE * a.w;
    int base = g_boff[c >> 8] + g_tmp[c];
    int pos = base + atomicAdd(&g_cnt[c], 1);
    g_csr_src[pos] = r;
    ((float4*)g_csr_alpha)[pos] = a;
}

// ---------------- kernel: fused online softmax + aggregation (warp/node) ------
// Chunked x4: 4 independent csr loads + 4 independent 128B xt gathers in
// flight, one rescale-exp per chunk. Self-resets g_deg/g_cnt for replay.
__global__ void k_node(float* __restrict__ out) {
    int gw = (int)(((long long)blockIdx.x * blockDim.x + threadIdx.x) >> 5);
    if (gw >= N_NODES) return;
    int lane = threadIdx.x & 31;
    int h = lane >> 3;
    int deg = g_deg[gw];
    int base = g_boff[gw >> 8] + g_tmp[gw];
    int end = base + deg;

    float m = -1e30f;
    float denom = 0.0f;
    float4 acc = make_float4(0.f, 0.f, 0.f, 0.f);

    int e = base;
    for (; e + 4 <= end; e += 4) {
        int s0 = __ldg(&g_csr_src[e + 0]);
        int s1 = __ldg(&g_csr_src[e + 1]);
        int s2 = __ldg(&g_csr_src[e + 2]);
        int s3 = __ldg(&g_csr_src[e + 3]);
        float a0 = __ldg(&g_csr_alpha[(size_t)(e + 0) * 4 + h]);
        float a1 = __ldg(&g_csr_alpha[(size_t)(e + 1) * 4 + h]);
        float a2 = __ldg(&g_csr_alpha[(size_t)(e + 2) * 4 + h]);
        float a3 = __ldg(&g_csr_alpha[(size_t)(e + 3) * 4 + h]);
        float4 v0 = __ldg(&((const float4*)g_xt)[(size_t)s0 * 32 + lane]);
        float4 v1 = __ldg(&((const float4*)g_xt)[(size_t)s1 * 32 + lane]);
        float4 v2 = __ldg(&((const float4*)g_xt)[(size_t)s2 * 32 + lane]);
        float4 v3 = __ldg(&((const float4*)g_xt)[(size_t)s3 * 32 + lane]);

        float mn = fmaxf(fmaxf(fmaxf(fmaxf(m, a0), a1), a2), a3);
        float sc = __expf(m - mn);          // 1 if no new max; 0 on first chunk
        float e0 = __expf(a0 - mn);
        float e1 = __expf(a1 - mn);
        float e2 = __expf(a2 - mn);
        float e3 = __expf(a3 - mn);
        m = mn;
        denom = fmaf(denom, sc, (e0 + e1) + (e2 + e3));
        acc.x = fmaf(v3.x, e3, fmaf(v2.x, e2, fmaf(v1.x, e1, fmaf(v0.x, e0, acc.x * sc))));
        acc.y = fmaf(v3.y, e3, fmaf(v2.y, e2, fmaf(v1.y, e1, fmaf(v0.y, e0, acc.y * sc))));
        acc.z = fmaf(v3.z, e3, fmaf(v2.z, e2, fmaf(v1.z, e1, fmaf(v0.z, e0, acc.z * sc))));
        acc.w = fmaf(v3.w, e3, fmaf(v2.w, e2, fmaf(v1.w, e1, fmaf(v0.w, e0, acc.w * sc))));
    }
    for (; e < end; e++) {
        int s = __ldg(&g_csr_src[e]);
        float a = __ldg(&g_csr_alpha[(size_t)e * 4 + h]);
        float4 v = __ldg(&((const float4*)g_xt)[(size_t)s * 32 + lane]);
        float mn = fmaxf(m, a);
        float sc = __expf(m - mn);
        float ex = __expf(a - mn);
        m = mn;
        denom = fmaf(denom, sc, ex);
        acc.x = fmaf(v.x, ex, acc.x * sc);
        acc.y = fmaf(v.y, ex, acc.y * sc);
        acc.z = fmaf(v.z, ex, acc.z * sc);
        acc.w = fmaf(v.w, ex, acc.w * sc);
    }

    float inv = 1.0f / (denom + 1e-16f);
    float4 o = make_float4(acc.x * inv, acc.y * inv, acc.z * inv, acc.w * inv);
    ((float4*)out)[(size_t)gw * 32 + lane] = o;

    if (lane == 0) {                // self-reset for next graph replay
        g_deg[gw] = 0;
        g_cnt[gw] = 0;
    }
}

// ---------------------------------------------------------------------------
extern "C" void kernel_launch(void* const* d_in, const int* in_sizes, int n_in,
                              void* d_out, int out_size) {
    const float* x  = (const float*)d_in[0];
    const int*   ei = (const int*)d_in[1];
    const float* ct = (const float*)d_in[2];
    const float* lw = (const float*)d_in[3];
    const float* lb = (const float*)d_in[4];
    const float* as = (const float*)d_in[5];
    const float* ad = (const float*)d_in[6];
    float* out = (float*)d_out;

    k_prep<<<64, 256>>>(lw, lb, as, ad, ct);
    k_xt<<<NBLK_X, 128>>>(x, ei);
    k_scanA<<<NBLK_A, 256>>>();
    k_scatter<<<(N_EDGES + 255) / 256, 256>>>(ei);
    {
        long long threads = (long long)N_NODES * 32;
        int blocks = (int)((threads + 255) / 256);
        k_node<<<blocks, 256>>>(out);
    }
}

// round 6
// speedup vs baseline: 2.7713x; 1.0651x over previous
#include <cuda_runtime.h>
#include <cuda_fp16.h>

#define N_NODES 50000
#define N_EDGES 600000
#define IN_CH 128
#define HC 128
#define HEADS 4
#define NEG_SLOPE 0.2f
#define NPB 32
#define NBLK_X 1563   // ceil(50000/32); 1563*384 >= 600000 edges for fused count
#define NBLK_A 196    // ceil(50000/256)

typedef unsigned long long ull;

// ---------------- scratch (device globals) -----------------------------------
__device__ float  g_Wt[IN_CH * HC];
__device__ float  g_bias[HC];
__device__ float  g_asrc[HC];
__device__ float  g_adst[HC];
__device__ __half g_xt_h[(size_t)N_NODES * HC];   // 12.8 MB, fp16 features
__device__ float  g_alpha_src[N_NODES * HEADS];
__device__ float  g_alpha_dst[N_NODES * HEADS];
__device__ int    g_deg[N_NODES];     // self-reset by k_node
__device__ int    g_cnt[N_NODES];     // self-reset by k_node
__device__ int    g_tmp[N_NODES];
__device__ int    g_bsum[NBLK_A];
__device__ int    g_boff[NBLK_A];
__device__ int    g_done;             // self-reset by scanA last block
__device__ int    g_csr_src[N_EDGES];

// ---------------- f32x2 packed-math helpers -----------------------------------
__device__ __forceinline__ ull pk2(float a, float b) {
    ull r; asm("mov.b64 %0, {%1, %2};" : "=l"(r) : "f"(a), "f"(b)); return r;
}
__device__ __forceinline__ void upk2(ull v, float& a, float& b) {
    asm("mov.b64 {%0, %1}, %2;" : "=f"(a), "=f"(b) : "l"(v));
}
__device__ __forceinline__ ull fma2(ull a, ull b, ull c) {
    ull d; asm("fma.rn.f32x2 %0, %1, %2, %3;" : "=l"(d) : "l"(a), "l"(b), "l"(c)); return d;
}
__device__ __forceinline__ ull mul2(ull a, ull b) {
    ull d; asm("mul.rn.f32x2 %0, %1, %2;" : "=l"(d) : "l"(a), "l"(b)); return d;
}
__device__ __forceinline__ ull add2(ull a, ull b) {
    ull d; asm("add.rn.f32x2 %0, %1, %2;" : "=l"(d) : "l"(a), "l"(b)); return d;
}

// ---------------- kernel 1: Bezier param interpolation -------------------------
__global__ void k_prep(const float* __restrict__ lw, const float* __restrict__ lb,
                       const float* __restrict__ as, const float* __restrict__ ad,
                       const float* __restrict__ ct) {
    float c0 = ct[0], c1 = ct[1], c2 = ct[2];
    int idx = blockIdx.x * blockDim.x + threadIdx.x;
    if (idx < IN_CH * HC) {
        int i = idx / HC;
        int o = idx % HC;
        g_Wt[idx] = c0 * lw[o * IN_CH + i]
                  + c1 * lw[IN_CH * HC + o * IN_CH + i]
                  + c2 * lw[2 * IN_CH * HC + o * IN_CH + i];
    }
    if (idx < HC) {
        g_bias[idx] = c0 * lb[idx] + c1 * lb[HC + idx] + c2 * lb[2 * HC + idx];
        g_asrc[idx] = c0 * as[idx] + c1 * as[HC + idx] + c2 * as[2 * HC + idx];
        g_adst[idx] = c0 * ad[idx] + c1 * ad[HC + idx] + c2 * ad[2 * HC + idx];
    }
}

// ---------------- kernel 2: node transform (f32x2 GEMM) + fused degree count --
__global__ void __launch_bounds__(128) k_xt(const float* __restrict__ x,
                                            const int* __restrict__ ei) {
    int t = threadIdx.x;

    // fused degree count: 3 edges per thread, overlapped with GEMM load phase
    {
        int ebase = blockIdx.x * 384;
        #pragma unroll
        for (int j = 0; j < 3; j++) {
            int e = ebase + j * 128 + t;
            if (e < N_EDGES) atomicAdd(&g_deg[ei[N_EDGES + e]], 1);
        }
    }

    __shared__ float2 xsp[16][IN_CH];
    int n0 = blockIdx.x * NPB;

    #pragma unroll
    for (int p = 0; p < 16; p++) {
        int na = n0 + p, nb = n0 + p + 16;
        float2 f;
        f.x = (na < N_NODES) ? x[(size_t)na * IN_CH + t] : 0.0f;
        f.y = (nb < N_NODES) ? x[(size_t)nb * IN_CH + t] : 0.0f;
        xsp[p][t] = f;
    }
    __syncthreads();

    ull acc[16];
    float b = g_bias[t];
    ull b2 = pk2(b, b);
    #pragma unroll
    for (int p = 0; p < 16; p++) acc[p] = b2;

    #pragma unroll 2
    for (int i = 0; i < IN_CH; i += 2) {
        float w0 = g_Wt[i * HC + t];
        float w1 = g_Wt[(i + 1) * HC + t];
        ull w02 = pk2(w0, w0);
        ull w12 = pk2(w1, w1);
        #pragma unroll
        for (int p = 0; p < 16; p++) {
            longlong2 xv = *reinterpret_cast<const longlong2*>(&xsp[p][i]);
            acc[p] = fma2((ull)xv.x, w02, acc[p]);
            acc[p] = fma2((ull)xv.y, w12, acc[p]);
        }
    }

    int h = t >> 5;
    float a_s = g_asrc[t];
    float a_d = g_adst[t];
    ull as2 = pk2(a_s, a_s);
    ull ad2 = pk2(a_d, a_d);

    #pragma unroll
    for (int p = 0; p < 16; p++) {
        int na = n0 + p, nb = n0 + p + 16;
        float lo, hi;
        upk2(acc[p], lo, hi);
        if (na < N_NODES) g_xt_h[(size_t)na * HC + t] = __float2half_rn(lo);
        if (nb < N_NODES) g_xt_h[(size_t)nb * HC + t] = __float2half_rn(hi);

        ull vs = mul2(acc[p], as2);
        ull vd = mul2(acc[p], ad2);
        #pragma unroll
        for (int off = 16; off > 0; off >>= 1) {
            vs = add2(vs, __shfl_xor_sync(0xffffffffu, vs, off));
            vd = add2(vd, __shfl_xor_sync(0xffffffffu, vd, off));
        }
        if ((t & 31) == 0) {
            float vsl, vsh, vdl, vdh;
            upk2(vs, vsl, vsh);
            upk2(vd, vdl, vdh);
            if (na < N_NODES) {
                g_alpha_src[na * HEADS + h] = vsl;
                g_alpha_dst[na * HEADS + h] = vdl;
            }
            if (nb < N_NODES) {
                g_alpha_src[nb * HEADS + h] = vsh;
                g_alpha_dst[nb * HEADS + h] = vdh;
            }
        }
    }
}

// ---------------- scan: per-block scan + last-block scan of block sums --------
__global__ void __launch_bounds__(256) k_scanA() {
    int tid = threadIdx.x;
    int n = blockIdx.x * 256 + tid;
    int v = (n < N_NODES) ? g_deg[n] : 0;
    int incl = v;
    #pragma unroll
    for (int d = 1; d < 32; d <<= 1) {
        int t = __shfl_up_sync(0xffffffffu, incl, d);
        if ((tid & 31) >= d) incl += t;
    }
    __shared__ int wsum[8];
    if ((tid & 31) == 31) wsum[tid >> 5] = incl;
    __syncthreads();
    if (tid < 8) {
        int s = wsum[tid];
        #pragma unroll
        for (int d = 1; d < 8; d <<= 1) {
            int t = __shfl_up_sync(0xffu, s, d);
            if (tid >= d) s += t;
        }
        wsum[tid] = s;
    }
    __syncthreads();
    int wid = tid >> 5;
    int excl = (wid > 0 ? wsum[wid - 1] : 0) + incl - v;
    if (n < N_NODES) g_tmp[n] = excl;

    __shared__ int amLast;
    if (tid == 0) {
        g_bsum[blockIdx.x] = wsum[7];
        __threadfence();
        int t = atomicAdd(&g_done, 1);
        amLast = (t == NBLK_A - 1);
    }
    __syncthreads();
    if (amLast) {
        __threadfence();
        int bv = (tid < NBLK_A) ? g_bsum[tid] : 0;
        int binc = bv;
        #pragma unroll
        for (int d = 1; d < 32; d <<= 1) {
            int t = __shfl_up_sync(0xffffffffu, binc, d);
            if ((tid & 31) >= d) binc += t;
        }
        if ((tid & 31) == 31) wsum[tid >> 5] = binc;
        __syncthreads();
        if (tid < 8) {
            int s = wsum[tid];
            #pragma unroll
            for (int d = 1; d < 8; d <<= 1) {
                int t = __shfl_up_sync(0xffu, s, d);
                if (tid >= d) s += t;
            }
            wsum[tid] = s;
        }
        __syncthreads();
        int bexcl = ((tid >> 5) > 0 ? wsum[(tid >> 5) - 1] : 0) + binc - bv;
        if (tid < NBLK_A) g_boff[tid] = bexcl;
        if (tid == 0) g_done = 0;   // self-reset for next replay
    }
}

// ---------------- kernel: minimal scatter (build CSR src list) ----------------
__global__ void k_scatter(const int* __restrict__ ei) {
    int e = blockIdx.x * blockDim.x + threadIdx.x;
    if (e >= N_EDGES) return;
    int r = __ldg(&ei[e]);
    int c = __ldg(&ei[N_EDGES + e]);
    int base = g_boff[c >> 8] + g_tmp[c];
    int pos = base + atomicAdd(&g_cnt[c], 1);
    g_csr_src[pos] = r;
}

// ---------------- kernel: fused online softmax + aggregation (warp/node) ------
// Chunked x4; fp16 xt gathers (half the L2 traffic), fp32 alpha gathers.
__global__ void k_node(float* __restrict__ out) {
    int gw = (int)(((long long)blockIdx.x * blockDim.x + threadIdx.x) >> 5);
    if (gw >= N_NODES) return;
    int lane = threadIdx.x & 31;
    int h = lane >> 3;
    int deg = g_deg[gw];
    int base = g_boff[gw >> 8] + g_tmp[gw];
    int end = base + deg;
    float ad = __ldg(&g_alpha_dst[gw * HEADS + h]);

    float m = -1e30f;
    float denom = 0.0f;
    float4 acc = make_float4(0.f, 0.f, 0.f, 0.f);

    const uint2* xt2 = (const uint2*)g_xt_h;   // 32 uint2 (8B) per 128-half row

    int e = base;
    for (; e + 4 <= end; e += 4) {
        int s0 = __ldg(&g_csr_src[e + 0]);
        int s1 = __ldg(&g_csr_src[e + 1]);
        int s2 = __ldg(&g_csr_src[e + 2]);
        int s3 = __ldg(&g_csr_src[e + 3]);
        float a0 = __ldg(&g_alpha_src[s0 * HEADS + h]) + ad;
        float a1 = __ldg(&g_alpha_src[s1 * HEADS + h]) + ad;
        float a2 = __ldg(&g_alpha_src[s2 * HEADS + h]) + ad;
        float a3 = __ldg(&g_alpha_src[s3 * HEADS + h]) + ad;
        uint2 u0 = __ldg(&xt2[(size_t)s0 * 32 + lane]);
        uint2 u1 = __ldg(&xt2[(size_t)s1 * 32 + lane]);
        uint2 u2 = __ldg(&xt2[(size_t)s2 * 32 + lane]);
        uint2 u3 = __ldg(&xt2[(size_t)s3 * 32 + lane]);
        a0 = (a0 > 0.f) ? a0 : NEG_SLOPE * a0;
        a1 = (a1 > 0.f) ? a1 : NEG_SLOPE * a1;
        a2 = (a2 > 0.f) ? a2 : NEG_SLOPE * a2;
        a3 = (a3 > 0.f) ? a3 : NEG_SLOPE * a3;

        float mn = fmaxf(fmaxf(fmaxf(fmaxf(m, a0), a1), a2), a3);
        float sc = __expf(m - mn);
        float e0 = __expf(a0 - mn);
        float e1 = __expf(a1 - mn);
        float e2 = __expf(a2 - mn);
        float e3 = __expf(a3 - mn);
        m = mn;
        denom = fmaf(denom, sc, (e0 + e1) + (e2 + e3));

        float2 p0a = __half22float2(*(const __half2*)&u0.x);
        float2 p0b = __half22float2(*(const __half2*)&u0.y);
        float2 p1a = __half22float2(*(const __half2*)&u1.x);
        float2 p1b = __half22float2(*(const __half2*)&u1.y);
        float2 p2a = __half22float2(*(const __half2*)&u2.x);
        float2 p2b = __half22float2(*(const __half2*)&u2.y);
        float2 p3a = __half22float2(*(const __half2*)&u3.x);
        float2 p3b = __half22float2(*(const __half2*)&u3.y);

        acc.x = fmaf(p3a.x, e3, fmaf(p2a.x, e2, fmaf(p1a.x, e1, fmaf(p0a.x, e0, acc.x * sc))));
        acc.y = fmaf(p3a.y, e3, fmaf(p2a.y, e2, fmaf(p1a.y, e1, fmaf(p0a.y, e0, acc.y * sc))));
        acc.z = fmaf(p3b.x, e3, fmaf(p2b.x, e2, fmaf(p1b.x, e1, fmaf(p0b.x, e0, acc.z * sc))));
        acc.w = fmaf(p3b.y, e3, fmaf(p2b.y, e2, fmaf(p1b.y, e1, fmaf(p0b.y, e0, acc.w * sc))));
    }
    for (; e < end; e++) {
        int s = __ldg(&g_csr_src[e]);
        float a = __ldg(&g_alpha_src[s * HEADS + h]) + ad;
        a = (a > 0.f) ? a : NEG_SLOPE * a;
        uint2 u = __ldg(&xt2[(size_t)s * 32 + lane]);
        float mn = fmaxf(m, a);
        float sc = __expf(m - mn);
        float ex = __expf(a - mn);
        m = mn;
        denom = fmaf(denom, sc, ex);
        float2 pa = __half22float2(*(const __half2*)&u.x);
        float2 pb = __half22float2(*(const __half2*)&u.y);
        acc.x = fmaf(pa.x, ex, acc.x * sc);
        acc.y = fmaf(pa.y, ex, acc.y * sc);
        acc.z = fmaf(pb.x, ex, acc.z * sc);
        acc.w = fmaf(pb.y, ex, acc.w * sc);
    }

    float inv = 1.0f / (denom + 1e-16f);
    float4 o = make_float4(acc.x * inv, acc.y * inv, acc.z * inv, acc.w * inv);
    ((float4*)out)[(size_t)gw * 32 + lane] = o;

    if (lane == 0) {                // self-reset for next graph replay
        g_deg[gw] = 0;
        g_cnt[gw] = 0;
    }
}

// ---------------------------------------------------------------------------
extern "C" void kernel_launch(void* const* d_in, const int* in_sizes, int n_in,
                              void* d_out, int out_size) {
    const float* x  = (const float*)d_in[0];
    const int*   ei = (const int*)d_in[1];
    const float* ct = (const float*)d_in[2];
    const float* lw = (const float*)d_in[3];
    const float* lb = (const float*)d_in[4];
    const float* as = (const float*)d_in[5];
    const float* ad = (const float*)d_in[6];
    float* out = (float*)d_out;

    k_prep<<<64, 256>>>(lw, lb, as, ad, ct);
    k_xt<<<NBLK_X, 128>>>(x, ei);
    k_scanA<<<NBLK_A, 256>>>();
    k_scatter<<<(N_EDGES + 255) / 256, 256>>>(ei);
    {
        long long threads = (long long)N_NODES * 32;
        int blocks = (int)((threads + 255) / 256);
        k_node<<<blocks, 256>>>(out);
    }
}